// round 1
// baseline (speedup 1.0000x reference)
#include <cuda_runtime.h>

#define IMGD 128
#define NPIX (IMGD*IMGD)
#define NIMG 40
#define TT 10
#define BB 4
#define HID 512
#define NL 6

// ---------------- scratch (static device globals; no allocation) ----------------
__device__ float g_buf0[(size_t)NIMG * 128 * NPIX];   // 336 MB ping
__device__ float g_buf1[(size_t)NIMG * 128 * NPIX];   // 336 MB pong
__device__ float g_img[BB * TT * 64];                 // fused image features
__device__ float g_h[2][NL][BB][HID];                 // LSTM h, double buffered by t parity
__device__ float g_c[2][NL][BB][HID];                 // LSTM c
__device__ float g_h5[TT][BB][HID];                   // top-layer h per timestep

// ---------------- zero initial LSTM state ----------------
__global__ void zero_state_kernel()
{
    int tid = blockIdx.x * blockDim.x + threadIdx.x;
    const int total = NL * BB * HID; // 12288 (= g_h[0] / g_c[0])
    if (tid < total) {
        ((float*)g_h)[tid] = 0.f;
        ((float*)g_c)[tid] = 0.f;
    }
}

// ---------------- implicit-GEMM 3x3 SAME conv + bias + relu ----------------
// M = OC, N = 16384 pixels, K = IC*9.  Tile: BM x 64 x 16, micro TM x 4.
template<int BM, int TM>
__global__ void conv_kernel(const float* __restrict__ ext_in, int in_sel, int out_sel,
                            const float* __restrict__ wt, const float* __restrict__ bias,
                            int IC, int OC)
{
    constexpr int BN = 64, BK = 16, TN = 4;
    constexpr int AST = BM + 4, BST = BN + 4;
    __shared__ __align__(16) float As[BK * AST];
    __shared__ __align__(16) float Bs[BK * BST];

    const float* inb = (in_sel == 2) ? ext_in : (in_sel == 0 ? g_buf0 : g_buf1);
    float* outb = (out_sel == 0) ? g_buf0 : g_buf1;

    const int n = blockIdx.z;
    const float* in = inb + (size_t)n * IC * NPIX;
    float* out = outb + (size_t)n * OC * NPIX;

    const int p0  = blockIdx.x * BN;
    const int oc0 = blockIdx.y * BM;
    const int py  = p0 >> 7;
    const int x0  = p0 & 127;
    const int K   = IC * 9;

    const int tid = threadIdx.x;
    const int tx = tid & 15, ty = tid >> 4;

    float acc[TM][TN];
#pragma unroll
    for (int r = 0; r < TM; ++r)
#pragma unroll
        for (int c = 0; c < TN; ++c) acc[r][c] = 0.f;

    for (int k0 = 0; k0 < K; k0 += BK) {
        // ---- load A (weights) : coalesced along K ----
#pragma unroll
        for (int e = tid; e < BM * BK; e += 256) {
            int j = e & (BK - 1);
            int i = e >> 4;
            int k = k0 + j, oc = oc0 + i;
            float v = 0.f;
            if (k < K && oc < OC) v = wt[oc * K + k];
            As[j * AST + i] = v;
        }
        // ---- load B (implicit im2col) : coalesced along x ----
#pragma unroll
        for (int e = tid; e < BK * BN; e += 256) {
            int j  = e >> 6;      // BN = 64
            int pp = e & 63;
            int k = k0 + j;
            float v = 0.f;
            if (k < K) {
                int ic = k / 9;
                int r  = k - ic * 9;
                int ky = r / 3;
                int kx = r - ky * 3;
                int iy = py + ky - 1;
                int ix = x0 + pp + kx - 1;
                if ((unsigned)iy < 128u && (unsigned)ix < 128u)
                    v = in[ic * NPIX + iy * IMGD + ix];
            }
            Bs[j * BST + pp] = v;
        }
        __syncthreads();

#pragma unroll
        for (int j = 0; j < BK; ++j) {
            float bv[TN];
            float4 b4 = *(const float4*)&Bs[j * BST + tx * TN];
            bv[0] = b4.x; bv[1] = b4.y; bv[2] = b4.z; bv[3] = b4.w;
            float av[TM];
            if constexpr (TM == 4) {
                float4 a4 = *(const float4*)&As[j * AST + ty * TM];
                av[0] = a4.x; av[1] = a4.y; av[2] = a4.z; av[3] = a4.w;
            } else {
#pragma unroll
                for (int r = 0; r < TM; ++r) av[r] = As[j * AST + ty * TM + r];
            }
#pragma unroll
            for (int r = 0; r < TM; ++r)
#pragma unroll
                for (int c = 0; c < TN; ++c)
                    acc[r][c] = fmaf(av[r], bv[c], acc[r][c]);
        }
        __syncthreads();
    }

    // ---- epilogue: bias + relu ----
#pragma unroll
    for (int r = 0; r < TM; ++r) {
        int oc = oc0 + ty * TM + r;
        if (oc < OC) {
            float bsv = bias[oc];
            float4 o;
            o.x = fmaxf(acc[r][0] + bsv, 0.f);
            o.y = fmaxf(acc[r][1] + bsv, 0.f);
            o.z = fmaxf(acc[r][2] + bsv, 0.f);
            o.w = fmaxf(acc[r][3] + bsv, 0.f);
            *(float4*)&out[oc * NPIX + p0 + tx * TN] = o;
        }
    }
}

// ---------------- spatial softmax over 128x128, expectation of pos grids ----------------
// reads g_buf1 (n, 16, 16384); writes g_img[n*64 + camOff + ch*2 + {0,1}]
__global__ void ssmax_kernel(int camOff)
{
    const int n = blockIdx.x;
    const int ch = blockIdx.y;
    const float* v = g_buf1 + ((size_t)n * 16 + ch) * NPIX;

    __shared__ float red[256];
    __shared__ float redx[256];
    __shared__ float redy[256];
    const int tid = threadIdx.x;

    float m = -1e30f;
    for (int p = tid; p < NPIX; p += 256) m = fmaxf(m, v[p]);
    red[tid] = m;
    __syncthreads();
    for (int s = 128; s > 0; s >>= 1) {
        if (tid < s) red[tid] = fmaxf(red[tid], red[tid + s]);
        __syncthreads();
    }
    m = red[0];
    __syncthreads();

    float s0 = 0.f, sx = 0.f, sy = 0.f;
    const float sc = 2.f / 127.f;
    for (int p = tid; p < NPIX; p += 256) {
        float e = expf(v[p] - m);
        float xx = (float)(p & 127) * sc - 1.f;
        float yy = (float)(p >> 7) * sc - 1.f;
        s0 += e;
        sx += e * xx;
        sy += e * yy;
    }
    red[tid] = s0; redx[tid] = sx; redy[tid] = sy;
    __syncthreads();
    for (int s = 128; s > 0; s >>= 1) {
        if (tid < s) {
            red[tid]  += red[tid + s];
            redx[tid] += redx[tid + s];
            redy[tid] += redy[tid + s];
        }
        __syncthreads();
    }
    if (tid == 0) {
        g_img[n * 64 + camOff + ch * 2 + 0] = redx[0] / red[0];
        g_img[n * 64 + camOff + ch * 2 + 1] = redy[0] / red[0];
    }
}

// ---------------- LSTM cell: one warp per hidden unit, 4 gates x 4 batch ----------------
__device__ __forceinline__ float sigf(float x) { return 1.f / (1.f + expf(-x)); }

__global__ void lstm_cell_kernel(const float* __restrict__ wih, const float* __restrict__ whh,
                                 const float* __restrict__ bih, const float* __restrict__ bhh,
                                 const float* __restrict__ states, int in_dim, int l, int t,
                                 int writeH5)
{
    __shared__ float xs[BB][576];
    __shared__ float hs[BB][HID];
    const int cur = t & 1, nxt = cur ^ 1;
    const int tid = threadIdx.x;
    const int imoff = in_dim - 64;

    for (int e = tid; e < BB * in_dim; e += blockDim.x) {
        int b = e / in_dim, k = e - b * in_dim;
        float v;
        if (k >= imoff)      v = g_img[(b * TT + t) * 64 + (k - imoff)];
        else if (l == 0)     v = states[(b * TT + t) * 6 + k];
        else                 v = g_h[nxt][l - 1][b][k];
        xs[b][k] = v;
    }
    for (int e = tid; e < BB * HID; e += blockDim.x) {
        int b = e >> 9, k = e & 511;
        hs[b][k] = g_h[cur][l][b][k];
    }
    __syncthreads();

    const int warp = tid >> 5, lane = tid & 31;
    const int u = blockIdx.x * (blockDim.x >> 5) + warp;   // 0..511

    float acc[4][4];
#pragma unroll
    for (int g = 0; g < 4; ++g)
#pragma unroll
        for (int b = 0; b < 4; ++b) acc[g][b] = 0.f;

    for (int k = lane; k < in_dim; k += 32) {
        float x0 = xs[0][k], x1 = xs[1][k], x2 = xs[2][k], x3 = xs[3][k];
#pragma unroll
        for (int g = 0; g < 4; ++g) {
            float w = wih[(u + g * HID) * in_dim + k];
            acc[g][0] += w * x0; acc[g][1] += w * x1;
            acc[g][2] += w * x2; acc[g][3] += w * x3;
        }
    }
    for (int k = lane; k < HID; k += 32) {
        float h0 = hs[0][k], h1 = hs[1][k], h2 = hs[2][k], h3 = hs[3][k];
#pragma unroll
        for (int g = 0; g < 4; ++g) {
            float w = whh[(u + g * HID) * HID + k];
            acc[g][0] += w * h0; acc[g][1] += w * h1;
            acc[g][2] += w * h2; acc[g][3] += w * h3;
        }
    }
#pragma unroll
    for (int off = 16; off; off >>= 1)
#pragma unroll
        for (int g = 0; g < 4; ++g)
#pragma unroll
            for (int b = 0; b < 4; ++b)
                acc[g][b] += __shfl_down_sync(0xffffffffu, acc[g][b], off);

    if (lane == 0) {
        float bi = bih[u]           + bhh[u];
        float bf = bih[u + HID]     + bhh[u + HID];
        float bg = bih[u + 2 * HID] + bhh[u + 2 * HID];
        float bo = bih[u + 3 * HID] + bhh[u + 3 * HID];
#pragma unroll
        for (int b = 0; b < 4; ++b) {
            float gi = sigf(acc[0][b] + bi);
            float gf = sigf(acc[1][b] + bf);
            float gg = tanhf(acc[2][b] + bg);
            float go = sigf(acc[3][b] + bo);
            float c2 = gf * g_c[cur][l][b][u] + gi * gg;
            float h2 = go * tanhf(c2);
            g_c[nxt][l][b][u] = c2;
            g_h[nxt][l][b][u] = h2;
            if (writeH5) g_h5[t][b][u] = h2;
        }
    }
}

// ---------------- final linear head ----------------
__global__ void outproj_kernel(const float* __restrict__ out_w, const float* __restrict__ out_b,
                               float* __restrict__ out)
{
    const int bt = blockIdx.x;         // 0..39
    const int b = bt / TT, t = bt - b * TT;
    const int warp = threadIdx.x >> 5, lane = threadIdx.x & 31;
    if (warp >= 6) return;
    float acc = 0.f;
    for (int k = lane; k < 576; k += 32) {
        float xv = (k < HID) ? g_h5[t][b][k] : g_img[(b * TT + t) * 64 + (k - HID)];
        acc += xv * out_w[warp * 576 + k];
    }
#pragma unroll
    for (int off = 16; off; off >>= 1) acc += __shfl_down_sync(0xffffffffu, acc, off);
    if (lane == 0) out[(b * TT + t) * 6 + warp] = acc + out_b[warp];
}

// ---------------- launcher ----------------
extern "C" void kernel_launch(void* const* d_in, const int* in_sizes, int n_in,
                              void* d_out, int out_size)
{
    const float* img_m  = (const float*)d_in[0];
    const float* img_s  = (const float*)d_in[1];
    const float* states = (const float*)d_in[2];

    const float* w[2][4];
    const float* bw[2][4];
    for (int c = 0; c < 2; ++c)
        for (int j = 0; j < 4; ++j) {
            w[c][j]  = (const float*)d_in[3 + c * 8 + j * 2];
            bw[c][j] = (const float*)d_in[3 + c * 8 + j * 2 + 1];
        }

    const float* wih0  = (const float*)d_in[19];
    const float* whh0  = (const float*)d_in[20];
    const float* bih0  = (const float*)d_in[21];
    const float* bhh0  = (const float*)d_in[22];
    const float* wih_r = (const float*)d_in[23];
    const float* whh_r = (const float*)d_in[24];
    const float* bih_r = (const float*)d_in[25];
    const float* bhh_r = (const float*)d_in[26];
    const float* out_w = (const float*)d_in[27];
    const float* out_b = (const float*)d_in[28];
    float* out = (float*)d_out;

    zero_state_kernel<<<48, 256>>>();

    for (int c = 0; c < 2; ++c) {
        const float* im = c ? img_s : img_m;
        // layer0: 3 -> 32   (ext -> buf0)
        conv_kernel<32, 2><<<dim3(256, 1, NIMG), 256>>>(im, 2, 0, w[c][0], bw[c][0], 3, 32);
        // layer1: 32 -> 64  (buf0 -> buf1)
        conv_kernel<64, 4><<<dim3(256, 1, NIMG), 256>>>(nullptr, 0, 1, w[c][1], bw[c][1], 32, 64);
        // layer2: 64 -> 128 (buf1 -> buf0)
        conv_kernel<64, 4><<<dim3(256, 2, NIMG), 256>>>(nullptr, 1, 0, w[c][2], bw[c][2], 64, 128);
        // layer3: 128 -> 16 (buf0 -> buf1)
        conv_kernel<32, 2><<<dim3(256, 1, NIMG), 256>>>(nullptr, 0, 1, w[c][3], bw[c][3], 128, 16);
        // spatial softmax reads buf1
        ssmax_kernel<<<dim3(NIMG, 16), 256>>>(c * 32);
    }

    for (int t = 0; t < TT; ++t) {
        lstm_cell_kernel<<<128, 128>>>(wih0, whh0, bih0, bhh0, states, 70, 0, t, 0);
        for (int l = 1; l < NL; ++l) {
            lstm_cell_kernel<<<128, 128>>>(wih_r + (size_t)(l - 1) * 2048 * 576,
                                           whh_r + (size_t)(l - 1) * 2048 * 512,
                                           bih_r + (l - 1) * 2048,
                                           bhh_r + (l - 1) * 2048,
                                           nullptr, 576, l, t, (l == NL - 1) ? 1 : 0);
        }
    }
    outproj_kernel<<<40, 192>>>(out_w, out_b, out);
}

// round 2
// speedup vs baseline: 1.5162x; 1.5162x over previous
#include <cuda_runtime.h>

#define IMGD 128
#define NPIX (IMGD*IMGD)
#define NIMG 40
#define TT 10
#define BB 4
#define HID 512
#define NL 6

// ---------------- scratch (static device globals; no allocation) ----------------
__device__ float g_buf0[(size_t)NIMG * 128 * NPIX];   // 336 MB ping
__device__ float g_buf1[(size_t)NIMG * 128 * NPIX];   // 336 MB pong
__device__ float g_img[BB * TT * 64];                 // fused image features
__device__ float g_h[2][NL][BB][HID];                 // LSTM h, double buffered by t parity
__device__ float g_c[2][NL][BB][HID];                 // LSTM c
__device__ float g_h5[TT][BB][HID];                   // top-layer h per timestep

// ---------------- zero initial LSTM state ----------------
__global__ void zero_state_kernel()
{
    int tid = blockIdx.x * blockDim.x + threadIdx.x;
    const int total = NL * BB * HID;
    if (tid < total) {
        ((float*)g_h)[tid] = 0.f;
        ((float*)g_c)[tid] = 0.f;
    }
}

// ---------------- layer0 conv (tiny K=27): old implicit-GEMM kernel ----------------
template<int BM, int TM>
__global__ void conv_kernel(const float* __restrict__ ext_in, int out_sel,
                            const float* __restrict__ wt, const float* __restrict__ bias,
                            int IC, int OC)
{
    constexpr int BN = 64, BK = 16, TN = 4;
    constexpr int AST = BM + 4, BST = BN + 4;
    __shared__ __align__(16) float As[BK * AST];
    __shared__ __align__(16) float Bs[BK * BST];

    float* outb = (out_sel == 0) ? g_buf0 : g_buf1;

    const int n = blockIdx.z;
    const float* in = ext_in + (size_t)n * IC * NPIX;
    float* out = outb + (size_t)n * OC * NPIX;

    const int p0  = blockIdx.x * BN;
    const int oc0 = blockIdx.y * BM;
    const int py  = p0 >> 7;
    const int x0  = p0 & 127;
    const int K   = IC * 9;

    const int tid = threadIdx.x;
    const int tx = tid & 15, ty = tid >> 4;

    float acc[TM][TN];
#pragma unroll
    for (int r = 0; r < TM; ++r)
#pragma unroll
        for (int c = 0; c < TN; ++c) acc[r][c] = 0.f;

    for (int k0 = 0; k0 < K; k0 += BK) {
#pragma unroll
        for (int e = tid; e < BM * BK; e += 256) {
            int j = e & (BK - 1);
            int i = e >> 4;
            int k = k0 + j, oc = oc0 + i;
            float v = 0.f;
            if (k < K && oc < OC) v = wt[oc * K + k];
            As[j * AST + i] = v;
        }
#pragma unroll
        for (int e = tid; e < BK * BN; e += 256) {
            int j  = e >> 6;
            int pp = e & 63;
            int k = k0 + j;
            float v = 0.f;
            if (k < K) {
                int ic = k / 9;
                int r  = k - ic * 9;
                int ky = r / 3;
                int kx = r - ky * 3;
                int iy = py + ky - 1;
                int ix = x0 + pp + kx - 1;
                if ((unsigned)iy < 128u && (unsigned)ix < 128u)
                    v = in[ic * NPIX + iy * IMGD + ix];
            }
            Bs[j * BST + pp] = v;
        }
        __syncthreads();

#pragma unroll
        for (int j = 0; j < BK; ++j) {
            float bv[TN];
            float4 b4 = *(const float4*)&Bs[j * BST + tx * TN];
            bv[0] = b4.x; bv[1] = b4.y; bv[2] = b4.z; bv[3] = b4.w;
            float av[TM];
#pragma unroll
            for (int r = 0; r < TM; ++r) av[r] = As[j * AST + ty * TM + r];
#pragma unroll
            for (int r = 0; r < TM; ++r)
#pragma unroll
                for (int c = 0; c < TN; ++c)
                    acc[r][c] = fmaf(av[r], bv[c], acc[r][c]);
        }
        __syncthreads();
    }

#pragma unroll
    for (int r = 0; r < TM; ++r) {
        int oc = oc0 + ty * TM + r;
        if (oc < OC) {
            float bsv = bias[oc];
            float4 o;
            o.x = fmaxf(acc[r][0] + bsv, 0.f);
            o.y = fmaxf(acc[r][1] + bsv, 0.f);
            o.z = fmaxf(acc[r][2] + bsv, 0.f);
            o.w = fmaxf(acc[r][3] + bsv, 0.f);
            *(float4*)&out[oc * NPIX + p0 + tx * TN] = o;
        }
    }
}

// ---------------- layers 1-3: SGEMM-style implicit conv, 8x8 micro-tiles ----------------
// One block = one image row (BN=128 pixels) x BM output channels. BK=8.
// THREADS must equal 2*BM ( = (BM/8)*(128/8) ).
template<int BM, int THREADS>
__global__ void __launch_bounds__(THREADS)
conv8_kernel(int in_sel, int out_sel,
             const float* __restrict__ wt, const float* __restrict__ bias,
             int IC, int OC)
{
    constexpr int BK = 8, BN = 128, TM = 8, TN = 8;
    constexpr int ASTR = BM + 4, BSTR = BN + 4;
    constexpr int TPR = (THREADS < 128) ? THREADS : 128;  // threads per B-row
    constexpr int PPT = 128 / TPR;                        // pixels/thread/row
    constexpr int RPP = THREADS / TPR;                    // rows per pass
    constexpr int NB  = (BK * BN) / THREADS;              // B elems per thread

    __shared__ __align__(16) float As[BK * ASTR];
    __shared__ __align__(16) float Bs[BK * BSTR];

    const float* inb = (in_sel == 0) ? g_buf0 : g_buf1;
    float* outb = (out_sel == 0) ? g_buf0 : g_buf1;

    const int n = blockIdx.z;
    const float* in = inb + (size_t)n * IC * NPIX;
    float* out = outb + (size_t)n * OC * NPIX;

    const int y   = blockIdx.x;           // image row
    const int oc0 = blockIdx.y * BM;
    const int K   = IC * 9;

    const int tid = threadIdx.x;
    const int tx = tid & 15, ty = tid >> 4;

    // A-load mapping: one float4 along K per thread
    const int a_oc = tid >> 1;
    const int a_kq = (tid & 1) * 4;
    const float* aPtr = wt + (size_t)(oc0 + a_oc) * K + a_kq;

    // B-load mapping
    const int jb = tid / TPR;
    const int pb = tid % TPR;

    float4 aReg;
    float  bReg[NB];

    auto loadB = [&](int k0) {
#pragma unroll
        for (int q = 0; q < BK / RPP; ++q) {
            int j  = jb + q * RPP;
            int k  = k0 + j;
            int ic = k / 9;
            int r  = k - ic * 9;
            int ky = r / 3;
            int kx = r - ky * 3;
            int iy = y + ky - 1;
            const float* rowp = in + ic * NPIX + iy * IMGD + kx - 1;
            bool rowok = ((unsigned)iy < 128u);
#pragma unroll
            for (int s = 0; s < PPT; ++s) {
                int pp = pb + s * TPR;
                int ix = pp + kx - 1;
                bReg[q * PPT + s] =
                    (rowok && ((unsigned)ix < 128u)) ? rowp[pp] : 0.f;
            }
        }
    };
    auto storeAB = [&]() {
        As[(a_kq + 0) * ASTR + a_oc] = aReg.x;
        As[(a_kq + 1) * ASTR + a_oc] = aReg.y;
        As[(a_kq + 2) * ASTR + a_oc] = aReg.z;
        As[(a_kq + 3) * ASTR + a_oc] = aReg.w;
#pragma unroll
        for (int q = 0; q < BK / RPP; ++q) {
            int j = jb + q * RPP;
#pragma unroll
            for (int s = 0; s < PPT; ++s) {
                int pp = pb + s * TPR;
                Bs[j * BSTR + pp] = bReg[q * PPT + s];
            }
        }
    };

    aReg = *(const float4*)aPtr;
    loadB(0);
    storeAB();
    __syncthreads();

    float acc[TM][TN];
#pragma unroll
    for (int r = 0; r < TM; ++r)
#pragma unroll
        for (int c = 0; c < TN; ++c) acc[r][c] = 0.f;

    for (int k0 = 0; k0 < K; k0 += BK) {
        const bool more = (k0 + BK) < K;
        if (more) {
            aReg = *(const float4*)(aPtr + k0 + BK);
            loadB(k0 + BK);
        }
#pragma unroll
        for (int j = 0; j < BK; ++j) {
            float4 a0 = *(const float4*)&As[j * ASTR + ty * TM];
            float4 a1 = *(const float4*)&As[j * ASTR + ty * TM + 4];
            float4 b0 = *(const float4*)&Bs[j * BSTR + tx * TN];
            float4 b1 = *(const float4*)&Bs[j * BSTR + tx * TN + 4];
            float av[8] = {a0.x, a0.y, a0.z, a0.w, a1.x, a1.y, a1.z, a1.w};
            float bv[8] = {b0.x, b0.y, b0.z, b0.w, b1.x, b1.y, b1.z, b1.w};
#pragma unroll
            for (int r = 0; r < TM; ++r)
#pragma unroll
                for (int c = 0; c < TN; ++c)
                    acc[r][c] = fmaf(av[r], bv[c], acc[r][c]);
        }
        __syncthreads();
        if (more) {
            storeAB();
            __syncthreads();
        }
    }

    // epilogue: bias + relu, vectorized stores
#pragma unroll
    for (int r = 0; r < TM; ++r) {
        int oc = oc0 + ty * TM + r;
        float bsv = bias[oc];
        float4 o0, o1;
        o0.x = fmaxf(acc[r][0] + bsv, 0.f);
        o0.y = fmaxf(acc[r][1] + bsv, 0.f);
        o0.z = fmaxf(acc[r][2] + bsv, 0.f);
        o0.w = fmaxf(acc[r][3] + bsv, 0.f);
        o1.x = fmaxf(acc[r][4] + bsv, 0.f);
        o1.y = fmaxf(acc[r][5] + bsv, 0.f);
        o1.z = fmaxf(acc[r][6] + bsv, 0.f);
        o1.w = fmaxf(acc[r][7] + bsv, 0.f);
        float* op = out + (size_t)oc * NPIX + (y << 7) + tx * TN;
        *(float4*)op       = o0;
        *(float4*)(op + 4) = o1;
    }
}

// ---------------- spatial softmax ----------------
__global__ void ssmax_kernel(int camOff)
{
    const int n = blockIdx.x;
    const int ch = blockIdx.y;
    const float* v = g_buf1 + ((size_t)n * 16 + ch) * NPIX;

    __shared__ float red[256];
    __shared__ float redx[256];
    __shared__ float redy[256];
    const int tid = threadIdx.x;

    float m = -1e30f;
    for (int p = tid; p < NPIX; p += 256) m = fmaxf(m, v[p]);
    red[tid] = m;
    __syncthreads();
    for (int s = 128; s > 0; s >>= 1) {
        if (tid < s) red[tid] = fmaxf(red[tid], red[tid + s]);
        __syncthreads();
    }
    m = red[0];
    __syncthreads();

    float s0 = 0.f, sx = 0.f, sy = 0.f;
    const float sc = 2.f / 127.f;
    for (int p = tid; p < NPIX; p += 256) {
        float e = expf(v[p] - m);
        float xx = (float)(p & 127) * sc - 1.f;
        float yy = (float)(p >> 7) * sc - 1.f;
        s0 += e;
        sx += e * xx;
        sy += e * yy;
    }
    red[tid] = s0; redx[tid] = sx; redy[tid] = sy;
    __syncthreads();
    for (int s = 128; s > 0; s >>= 1) {
        if (tid < s) {
            red[tid]  += red[tid + s];
            redx[tid] += redx[tid + s];
            redy[tid] += redy[tid + s];
        }
        __syncthreads();
    }
    if (tid == 0) {
        g_img[n * 64 + camOff + ch * 2 + 0] = redx[0] / red[0];
        g_img[n * 64 + camOff + ch * 2 + 1] = redy[0] / red[0];
    }
}

// ---------------- LSTM cell ----------------
__device__ __forceinline__ float sigf(float x) { return 1.f / (1.f + expf(-x)); }

__global__ void lstm_cell_kernel(const float* __restrict__ wih, const float* __restrict__ whh,
                                 const float* __restrict__ bih, const float* __restrict__ bhh,
                                 const float* __restrict__ states, int in_dim, int l, int t,
                                 int writeH5)
{
    __shared__ float xs[BB][576];
    __shared__ float hs[BB][HID];
    const int cur = t & 1, nxt = cur ^ 1;
    const int tid = threadIdx.x;
    const int imoff = in_dim - 64;

    for (int e = tid; e < BB * in_dim; e += blockDim.x) {
        int b = e / in_dim, k = e - b * in_dim;
        float v;
        if (k >= imoff)      v = g_img[(b * TT + t) * 64 + (k - imoff)];
        else if (l == 0)     v = states[(b * TT + t) * 6 + k];
        else                 v = g_h[nxt][l - 1][b][k];
        xs[b][k] = v;
    }
    for (int e = tid; e < BB * HID; e += blockDim.x) {
        int b = e >> 9, k = e & 511;
        hs[b][k] = g_h[cur][l][b][k];
    }
    __syncthreads();

    const int warp = tid >> 5, lane = tid & 31;
    const int u = blockIdx.x * (blockDim.x >> 5) + warp;

    float acc[4][4];
#pragma unroll
    for (int g = 0; g < 4; ++g)
#pragma unroll
        for (int b = 0; b < 4; ++b) acc[g][b] = 0.f;

    for (int k = lane; k < in_dim; k += 32) {
        float x0 = xs[0][k], x1 = xs[1][k], x2 = xs[2][k], x3 = xs[3][k];
#pragma unroll
        for (int g = 0; g < 4; ++g) {
            float w = wih[(u + g * HID) * in_dim + k];
            acc[g][0] += w * x0; acc[g][1] += w * x1;
            acc[g][2] += w * x2; acc[g][3] += w * x3;
        }
    }
    for (int k = lane; k < HID; k += 32) {
        float h0 = hs[0][k], h1 = hs[1][k], h2 = hs[2][k], h3 = hs[3][k];
#pragma unroll
        for (int g = 0; g < 4; ++g) {
            float w = whh[(u + g * HID) * HID + k];
            acc[g][0] += w * h0; acc[g][1] += w * h1;
            acc[g][2] += w * h2; acc[g][3] += w * h3;
        }
    }
#pragma unroll
    for (int off = 16; off; off >>= 1)
#pragma unroll
        for (int g = 0; g < 4; ++g)
#pragma unroll
            for (int b = 0; b < 4; ++b)
                acc[g][b] += __shfl_down_sync(0xffffffffu, acc[g][b], off);

    if (lane == 0) {
        float bi = bih[u]           + bhh[u];
        float bf = bih[u + HID]     + bhh[u + HID];
        float bg = bih[u + 2 * HID] + bhh[u + 2 * HID];
        float bo = bih[u + 3 * HID] + bhh[u + 3 * HID];
#pragma unroll
        for (int b = 0; b < 4; ++b) {
            float gi = sigf(acc[0][b] + bi);
            float gf = sigf(acc[1][b] + bf);
            float gg = tanhf(acc[2][b] + bg);
            float go = sigf(acc[3][b] + bo);
            float c2 = gf * g_c[cur][l][b][u] + gi * gg;
            float h2 = go * tanhf(c2);
            g_c[nxt][l][b][u] = c2;
            g_h[nxt][l][b][u] = h2;
            if (writeH5) g_h5[t][b][u] = h2;
        }
    }
}

// ---------------- final linear head ----------------
__global__ void outproj_kernel(const float* __restrict__ out_w, const float* __restrict__ out_b,
                               float* __restrict__ out)
{
    const int bt = blockIdx.x;
    const int b = bt / TT, t = bt - b * TT;
    const int warp = threadIdx.x >> 5, lane = threadIdx.x & 31;
    if (warp >= 6) return;
    float acc = 0.f;
    for (int k = lane; k < 576; k += 32) {
        float xv = (k < HID) ? g_h5[t][b][k] : g_img[(b * TT + t) * 64 + (k - HID)];
        acc += xv * out_w[warp * 576 + k];
    }
#pragma unroll
    for (int off = 16; off; off >>= 1) acc += __shfl_down_sync(0xffffffffu, acc, off);
    if (lane == 0) out[(b * TT + t) * 6 + warp] = acc + out_b[warp];
}

// ---------------- launcher ----------------
extern "C" void kernel_launch(void* const* d_in, const int* in_sizes, int n_in,
                              void* d_out, int out_size)
{
    const float* img_m  = (const float*)d_in[0];
    const float* img_s  = (const float*)d_in[1];
    const float* states = (const float*)d_in[2];

    const float* w[2][4];
    const float* bw[2][4];
    for (int c = 0; c < 2; ++c)
        for (int j = 0; j < 4; ++j) {
            w[c][j]  = (const float*)d_in[3 + c * 8 + j * 2];
            bw[c][j] = (const float*)d_in[3 + c * 8 + j * 2 + 1];
        }

    const float* wih0  = (const float*)d_in[19];
    const float* whh0  = (const float*)d_in[20];
    const float* bih0  = (const float*)d_in[21];
    const float* bhh0  = (const float*)d_in[22];
    const float* wih_r = (const float*)d_in[23];
    const float* whh_r = (const float*)d_in[24];
    const float* bih_r = (const float*)d_in[25];
    const float* bhh_r = (const float*)d_in[26];
    const float* out_w = (const float*)d_in[27];
    const float* out_b = (const float*)d_in[28];
    float* out = (float*)d_out;

    zero_state_kernel<<<48, 256>>>();

    for (int c = 0; c < 2; ++c) {
        const float* im = c ? img_s : img_m;
        // layer0: 3 -> 32   (ext -> buf0), K=27 (not multiple of 8) -> old kernel
        conv_kernel<32, 2><<<dim3(256, 1, NIMG), 256>>>(im, 0, w[c][0], bw[c][0], 3, 32);
        // layer1: 32 -> 64  (buf0 -> buf1), K=288
        conv8_kernel<64, 128><<<dim3(128, 1, NIMG), 128>>>(0, 1, w[c][1], bw[c][1], 32, 64);
        // layer2: 64 -> 128 (buf1 -> buf0), K=576
        conv8_kernel<128, 256><<<dim3(128, 1, NIMG), 256>>>(1, 0, w[c][2], bw[c][2], 64, 128);
        // layer3: 128 -> 16 (buf0 -> buf1), K=1152
        conv8_kernel<16, 32><<<dim3(128, 1, NIMG), 32>>>(0, 1, w[c][3], bw[c][3], 128, 16);
        // spatial softmax reads buf1
        ssmax_kernel<<<dim3(NIMG, 16), 256>>>(c * 32);
    }

    for (int t = 0; t < TT; ++t) {
        lstm_cell_kernel<<<128, 128>>>(wih0, whh0, bih0, bhh0, states, 70, 0, t, 0);
        for (int l = 1; l < NL; ++l) {
            lstm_cell_kernel<<<128, 128>>>(wih_r + (size_t)(l - 1) * 2048 * 576,
                                           whh_r + (size_t)(l - 1) * 2048 * 512,
                                           bih_r + (l - 1) * 2048,
                                           bhh_r + (l - 1) * 2048,
                                           nullptr, 576, l, t, (l == NL - 1) ? 1 : 0);
        }
    }
    outproj_kernel<<<40, 192>>>(out_w, out_b, out);
}